// round 1
// baseline (speedup 1.0000x reference)
#include <cuda_runtime.h>

// Problem dims
#define B_   64
#define N_   256
#define INDIM  512
#define OUTDIM 512
#define KSLOT  8
#define DKDIM  64   // OUTDIM / KSLOT

// Intermediate h = relu(X @ W + bias): 64*256*512 floats = 32 MB device scratch
__device__ float g_h[B_ * N_ * OUTDIM];

// ----------------------------------------------------------------------------
// Kernel 1: H[M=16384, 512] = relu(X[16384,512] @ W[512,512] + bias[512])
// 64x64 output tile, BK=32, 256 threads, 4x4 accum per thread.
// ----------------------------------------------------------------------------
__global__ __launch_bounds__(256) void linear_relu_kernel(
    const float* __restrict__ X,
    const float* __restrict__ W,
    const float* __restrict__ bias,
    float* __restrict__ H)
{
    constexpr int BM = 64, BN = 64, BK = 32;
    constexpr int Kdim = INDIM, Ndim = OUTDIM;

    __shared__ float As[BM][BK + 1];   // +1 pad: conflict-free column reads
    __shared__ float Bs[BK][BN];

    const int tid = threadIdx.x;
    const int tx = tid & 15;          // 0..15 -> 4 cols each
    const int ty = tid >> 4;          // 0..15 -> 4 rows each
    const int rowBase = blockIdx.y * BM;
    const int colBase = blockIdx.x * BN;

    float acc[4][4] = {};

    for (int k0 = 0; k0 < Kdim; k0 += BK) {
        // Load A tile 64x32 (coalesced: consecutive tid -> consecutive k)
        #pragma unroll
        for (int i = 0; i < (BM * BK) / 256; i++) {
            int idx = tid + i * 256;
            int r = idx / BK, c = idx % BK;
            As[r][c] = X[(rowBase + r) * Kdim + k0 + c];
        }
        // Load B tile 32x64 (coalesced)
        #pragma unroll
        for (int i = 0; i < (BK * BN) / 256; i++) {
            int idx = tid + i * 256;
            int r = idx / BN, c = idx % BN;
            Bs[r][c] = W[(k0 + r) * Ndim + colBase + c];
        }
        __syncthreads();

        #pragma unroll
        for (int kk = 0; kk < BK; kk++) {
            float a0 = As[ty * 4 + 0][kk];
            float a1 = As[ty * 4 + 1][kk];
            float a2 = As[ty * 4 + 2][kk];
            float a3 = As[ty * 4 + 3][kk];
            float4 b4 = *reinterpret_cast<const float4*>(&Bs[kk][tx * 4]);
            acc[0][0] = fmaf(a0, b4.x, acc[0][0]); acc[0][1] = fmaf(a0, b4.y, acc[0][1]);
            acc[0][2] = fmaf(a0, b4.z, acc[0][2]); acc[0][3] = fmaf(a0, b4.w, acc[0][3]);
            acc[1][0] = fmaf(a1, b4.x, acc[1][0]); acc[1][1] = fmaf(a1, b4.y, acc[1][1]);
            acc[1][2] = fmaf(a1, b4.z, acc[1][2]); acc[1][3] = fmaf(a1, b4.w, acc[1][3]);
            acc[2][0] = fmaf(a2, b4.x, acc[2][0]); acc[2][1] = fmaf(a2, b4.y, acc[2][1]);
            acc[2][2] = fmaf(a2, b4.z, acc[2][2]); acc[2][3] = fmaf(a2, b4.w, acc[2][3]);
            acc[3][0] = fmaf(a3, b4.x, acc[3][0]); acc[3][1] = fmaf(a3, b4.y, acc[3][1]);
            acc[3][2] = fmaf(a3, b4.z, acc[3][2]); acc[3][3] = fmaf(a3, b4.w, acc[3][3]);
        }
        __syncthreads();
    }

    // Epilogue: bias + ReLU, store
    #pragma unroll
    for (int i = 0; i < 4; i++) {
        int r = rowBase + ty * 4 + i;
        #pragma unroll
        for (int j = 0; j < 4; j++) {
            int c = colBase + tx * 4 + j;
            float v = acc[i][j] + bias[c];
            H[r * Ndim + c] = v > 0.0f ? v : 0.0f;
        }
    }
}

// ----------------------------------------------------------------------------
// Kernel 2: out[b,n,k*64+d] = sum_m adj[b,k,n,m] * H[b,m,k*64+d]
// Per (b,k): 256x256 @ 256x64. Grid (ntile=4, k=8, b=64); 64x64 tile, BK=32.
// ----------------------------------------------------------------------------
__global__ __launch_bounds__(256) void aggregate_kernel(
    const float* __restrict__ adj,
    const float* __restrict__ H,
    float* __restrict__ out)
{
    constexpr int BM = 64, BK = 32;    // BN = 64 = DKDIM (full d range)

    __shared__ float As[BM][BK + 1];
    __shared__ float Bs[BK][DKDIM];

    const int tid = threadIdx.x;
    const int tx = tid & 15;
    const int ty = tid >> 4;
    const int nBase = blockIdx.x * BM;
    const int k = blockIdx.y;
    const int b = blockIdx.z;

    // adj[b][k] base: (b*KSLOT + k) * N_ * N_
    const float* A = adj + (size_t)(b * KSLOT + k) * N_ * N_;
    // H rows for batch b, column offset k*DKDIM
    const float* Hb = H + (size_t)b * N_ * OUTDIM + k * DKDIM;

    float acc[4][4] = {};

    for (int m0 = 0; m0 < N_; m0 += BK) {
        // A tile: adj rows (nBase+r), cols (m0+c)  -- 64x32
        #pragma unroll
        for (int i = 0; i < (BM * BK) / 256; i++) {
            int idx = tid + i * 256;
            int r = idx / BK, c = idx % BK;
            As[r][c] = A[(nBase + r) * N_ + m0 + c];
        }
        // B tile: H rows (m0+r), cols d=c (row stride OUTDIM) -- 32x64
        #pragma unroll
        for (int i = 0; i < (BK * DKDIM) / 256; i++) {
            int idx = tid + i * 256;
            int r = idx / DKDIM, c = idx % DKDIM;
            Bs[r][c] = Hb[(m0 + r) * OUTDIM + c];
        }
        __syncthreads();

        #pragma unroll
        for (int kk = 0; kk < BK; kk++) {
            float a0 = As[ty * 4 + 0][kk];
            float a1 = As[ty * 4 + 1][kk];
            float a2 = As[ty * 4 + 2][kk];
            float a3 = As[ty * 4 + 3][kk];
            float4 b4 = *reinterpret_cast<const float4*>(&Bs[kk][tx * 4]);
            acc[0][0] = fmaf(a0, b4.x, acc[0][0]); acc[0][1] = fmaf(a0, b4.y, acc[0][1]);
            acc[0][2] = fmaf(a0, b4.z, acc[0][2]); acc[0][3] = fmaf(a0, b4.w, acc[0][3]);
            acc[1][0] = fmaf(a1, b4.x, acc[1][0]); acc[1][1] = fmaf(a1, b4.y, acc[1][1]);
            acc[1][2] = fmaf(a1, b4.z, acc[1][2]); acc[1][3] = fmaf(a1, b4.w, acc[1][3]);
            acc[2][0] = fmaf(a2, b4.x, acc[2][0]); acc[2][1] = fmaf(a2, b4.y, acc[2][1]);
            acc[2][2] = fmaf(a2, b4.z, acc[2][2]); acc[2][3] = fmaf(a2, b4.w, acc[2][3]);
            acc[3][0] = fmaf(a3, b4.x, acc[3][0]); acc[3][1] = fmaf(a3, b4.y, acc[3][1]);
            acc[3][2] = fmaf(a3, b4.z, acc[3][2]); acc[3][3] = fmaf(a3, b4.w, acc[3][3]);
        }
        __syncthreads();
    }

    // Write out[b, n, k*64 + d]
    float* O = out + (size_t)b * N_ * OUTDIM + k * DKDIM;
    #pragma unroll
    for (int i = 0; i < 4; i++) {
        int n = nBase + ty * 4 + i;
        #pragma unroll
        for (int j = 0; j < 4; j++) {
            int d = tx * 4 + j;
            O[n * OUTDIM + d] = acc[i][j];
        }
    }
}

// ----------------------------------------------------------------------------
extern "C" void kernel_launch(void* const* d_in, const int* in_sizes, int n_in,
                              void* d_out, int out_size)
{
    const float* node_feats = (const float*)d_in[0];  // (64,256,512)
    const float* adj        = (const float*)d_in[1];  // (64,8,256,256)
    const float* weight     = (const float*)d_in[2];  // (512,512)
    const float* bias       = (const float*)d_in[3];  // (512,)
    float* out = (float*)d_out;

    float* H;
    cudaGetSymbolAddress((void**)&H, g_h);

    // Stage 1: linear + relu -> H
    {
        dim3 grid(OUTDIM / 64, (B_ * N_) / 64);  // (8, 256)
        linear_relu_kernel<<<grid, 256>>>(node_feats, weight, bias, H);
    }
    // Stage 2: per-(b,k) aggregation -> out
    {
        dim3 grid(N_ / 64, KSLOT, B_);           // (4, 8, 64)
        aggregate_kernel<<<grid, 256>>>(adj, H, out);
    }
}

// round 3
// speedup vs baseline: 2.1528x; 2.1528x over previous
#include <cuda_runtime.h>
#include <cstdint>

#define B_     64
#define N_     256
#define INDIM  512
#define OUTDIM 512
#define KSLOT  8
#define DKDIM  64

// Scratch: H^T [b][feature][m] and W^T [out][in]
__device__ float g_ht[(size_t)B_ * OUTDIM * N_];
__device__ float g_wt[OUTDIM * INDIM];

// ---------------------------------------------------------------------------
__device__ __forceinline__ uint32_t tf32u(float x) {
    uint32_t r; asm("cvt.rna.tf32.f32 %0, %1;" : "=r"(r) : "f"(x)); return r;
}

__device__ __forceinline__ void mma_tf32(float c[4], const uint32_t a[4], const uint32_t b[2]) {
    asm volatile(
        "mma.sync.aligned.m16n8k8.row.col.f32.tf32.tf32.f32 "
        "{%0,%1,%2,%3}, {%4,%5,%6,%7}, {%8,%9}, {%0,%1,%2,%3};"
        : "+f"(c[0]), "+f"(c[1]), "+f"(c[2]), "+f"(c[3])
        : "r"(a[0]), "r"(a[1]), "r"(a[2]), "r"(a[3]), "r"(b[0]), "r"(b[1]));
}

// Permuted k-layout within a 32-wide chunk row:
//   element k (0..31) stored at float column  (k>>3)*8 + (k&3)*2 + ((k&7)>>2)
// so (k, k+4) are adjacent -> one LDS.64 per fragment pair.
// Row pitch 36 floats (144B) -> fragment LDS.64 is exactly 2-phase.
#define PITCH 36

// ---------------------------------------------------------------------------
// Kernel 0: W^T  (Wt[n][k] = W[k][n])
// ---------------------------------------------------------------------------
__global__ __launch_bounds__(256) void wt_kernel(const float* __restrict__ W,
                                                 float* __restrict__ Wt) {
    __shared__ float t[32][33];
    const int bx = blockIdx.x * 32;   // out (n)
    const int by = blockIdx.y * 32;   // in  (k)
    #pragma unroll
    for (int i = 0; i < 4; i++)
        t[threadIdx.y + i * 8][threadIdx.x] = W[(size_t)(by + threadIdx.y + i * 8) * OUTDIM + bx + threadIdx.x];
    __syncthreads();
    #pragma unroll
    for (int i = 0; i < 4; i++)
        Wt[(size_t)(bx + threadIdx.y + i * 8) * INDIM + by + threadIdx.x] = t[threadIdx.x][threadIdx.y + i * 8];
}

// ---------------------------------------------------------------------------
// Stage 1: HT[b][f][m] = relu( X @ W + bias )
// CTA 128(m) x 128(f), 8 warps (4 m x 2 f), warp tile 32x64. K chunks of 32.
// ---------------------------------------------------------------------------
__global__ __launch_bounds__(256) void s1_linear_mma(
    const float* __restrict__ X, const float* __restrict__ Wt,
    const float* __restrict__ bias, float* __restrict__ HT)
{
    __shared__ uint32_t As[128][PITCH];   // X tile   (rows m, perm-k cols)
    __shared__ uint32_t Bs[128][PITCH];   // Wt tile  (rows f, perm-k cols)

    const int tid = threadIdx.x;
    const int warpId = tid >> 5, lid = tid & 31;
    const int gid = lid >> 2, tig = lid & 3;
    const int wr = warpId & 3;            // m: 4 warps * 32
    const int wc = warpId >> 2;           // f: 2 warps * 64
    const int mBase = blockIdx.y * 128;
    const int nBase = blockIdx.x * 128;

    float c[2][8][4];
    #pragma unroll
    for (int mt = 0; mt < 2; mt++)
        #pragma unroll
        for (int nt = 0; nt < 8; nt++)
            #pragma unroll
            for (int i = 0; i < 4; i++) c[mt][nt][i] = 0.0f;

    // staging regs
    float4 ar[4], br[4];

    // thread -> (row, k-quad) for staging: 1024 float4 per tile, 4/thread
    // idx = tid + it*256 ; r = idx>>3 ; c4 = idx&7 ; k = c4*4
    auto loadA = [&](int k0) {
        #pragma unroll
        for (int it = 0; it < 4; it++) {
            int idx = tid + it * 256;
            int r = idx >> 3, c4 = idx & 7;
            ar[it] = *reinterpret_cast<const float4*>(X + (size_t)(mBase + r) * INDIM + k0 + c4 * 4);
        }
    };
    auto loadB = [&](int k0) {
        #pragma unroll
        for (int it = 0; it < 4; it++) {
            int idx = tid + it * 256;
            int r = idx >> 3, c4 = idx & 7;
            br[it] = *reinterpret_cast<const float4*>(Wt + (size_t)(nBase + r) * INDIM + k0 + c4 * 4);
        }
    };
    auto stsAll = [&]() {
        #pragma unroll
        for (int it = 0; it < 4; it++) {
            int idx = tid + it * 256;
            int r = idx >> 3, c4 = idx & 7;
            int ks = c4 >> 1, h = c4 & 1;
            uint32_t* s = &As[r][ks * 8 + h];
            s[0] = tf32u(ar[it].x); s[2] = tf32u(ar[it].y);
            s[4] = tf32u(ar[it].z); s[6] = tf32u(ar[it].w);
            uint32_t* s2 = &Bs[r][ks * 8 + h];
            s2[0] = tf32u(br[it].x); s2[2] = tf32u(br[it].y);
            s2[4] = tf32u(br[it].z); s2[6] = tf32u(br[it].w);
        }
    };

    loadA(0); loadB(0);
    for (int cc = 0; cc < INDIM / 32; cc++) {
        stsAll();
        __syncthreads();
        if (cc + 1 < INDIM / 32) { loadA((cc + 1) * 32); loadB((cc + 1) * 32); }

        #pragma unroll
        for (int ks = 0; ks < 4; ks++) {
            uint32_t bfr[8][2];
            #pragma unroll
            for (int nt = 0; nt < 8; nt++) {
                uint2 t = *reinterpret_cast<const uint2*>(&Bs[wc * 64 + nt * 8 + gid][ks * 8 + tig * 2]);
                bfr[nt][0] = t.x; bfr[nt][1] = t.y;
            }
            uint32_t afr[2][4];
            #pragma unroll
            for (int mt = 0; mt < 2; mt++) {
                int r0 = wr * 32 + mt * 16 + gid;
                uint2 t0 = *reinterpret_cast<const uint2*>(&As[r0][ks * 8 + tig * 2]);
                uint2 t1 = *reinterpret_cast<const uint2*>(&As[r0 + 8][ks * 8 + tig * 2]);
                afr[mt][0] = t0.x; afr[mt][2] = t0.y;
                afr[mt][1] = t1.x; afr[mt][3] = t1.y;
            }
            #pragma unroll
            for (int mt = 0; mt < 2; mt++)
                #pragma unroll
                for (int nt = 0; nt < 8; nt++)
                    mma_tf32(c[mt][nt], afr[mt], bfr[nt]);
        }
        __syncthreads();
    }

    // Epilogue: bias + relu, write transposed HT[b][f][m] (32B sectors per quad)
    const int batch = mBase >> 8;                 // 128-tile never straddles batch
    float* dst = HT + (size_t)batch * OUTDIM * N_;
    const int mloc = (mBase & 255) + wr * 32;
    #pragma unroll
    for (int mt = 0; mt < 2; mt++) {
        int m0 = mloc + mt * 16 + gid;
        #pragma unroll
        for (int nt = 0; nt < 8; nt++) {
            int f0 = nBase + wc * 64 + nt * 8 + tig * 2;
            float b0 = bias[f0], b1 = bias[f0 + 1];
            dst[(size_t)f0 * N_ + m0]           = fmaxf(c[mt][nt][0] + b0, 0.0f);
            dst[(size_t)(f0 + 1) * N_ + m0]     = fmaxf(c[mt][nt][1] + b1, 0.0f);
            dst[(size_t)f0 * N_ + m0 + 8]       = fmaxf(c[mt][nt][2] + b0, 0.0f);
            dst[(size_t)(f0 + 1) * N_ + m0 + 8] = fmaxf(c[mt][nt][3] + b1, 0.0f);
        }
    }
}

// ---------------------------------------------------------------------------
// Stage 2: out[b,n,k*64+d] = sum_m adj[b,k,n,m] * HT[b][k*64+d][m]
// CTA 128(n) x 64(d), 8 warps (4 n x 2 d), warp tile 32x32. m chunks of 32.
// ---------------------------------------------------------------------------
__global__ __launch_bounds__(256) void s2_aggregate_mma(
    const float* __restrict__ adj, const float* __restrict__ HT,
    float* __restrict__ out)
{
    __shared__ uint32_t As[128][PITCH];   // adj tile (rows n, perm-m cols)
    __shared__ uint32_t Bs[64][PITCH];    // HT tile  (rows d, perm-m cols)

    const int tid = threadIdx.x;
    const int warpId = tid >> 5, lid = tid & 31;
    const int gid = lid >> 2, tig = lid & 3;
    const int wr = warpId & 3;            // n: 4 warps * 32
    const int wc = warpId >> 2;           // d: 2 warps * 32
    const int nBase = blockIdx.x * 128;
    const int kslot = blockIdx.y;
    const int bIdx  = blockIdx.z;

    const float* A  = adj + (size_t)(bIdx * KSLOT + kslot) * N_ * N_;
    const float* Bp = HT + ((size_t)bIdx * OUTDIM + kslot * DKDIM) * N_;

    float c[2][4][4];
    #pragma unroll
    for (int mt = 0; mt < 2; mt++)
        #pragma unroll
        for (int nt = 0; nt < 4; nt++)
            #pragma unroll
            for (int i = 0; i < 4; i++) c[mt][nt][i] = 0.0f;

    float4 ar[4], br[2];

    auto loadA = [&](int m0) {
        #pragma unroll
        for (int it = 0; it < 4; it++) {
            int idx = tid + it * 256;
            int r = idx >> 3, c4 = idx & 7;
            ar[it] = *reinterpret_cast<const float4*>(A + (size_t)(nBase + r) * N_ + m0 + c4 * 4);
        }
    };
    auto loadB = [&](int m0) {
        #pragma unroll
        for (int it = 0; it < 2; it++) {
            int idx = tid + it * 256;
            int r = idx >> 3, c4 = idx & 7;
            br[it] = *reinterpret_cast<const float4*>(Bp + (size_t)r * N_ + m0 + c4 * 4);
        }
    };
    auto stsAll = [&]() {
        #pragma unroll
        for (int it = 0; it < 4; it++) {
            int idx = tid + it * 256;
            int r = idx >> 3, c4 = idx & 7;
            int ks = c4 >> 1, h = c4 & 1;
            uint32_t* s = &As[r][ks * 8 + h];
            s[0] = tf32u(ar[it].x); s[2] = tf32u(ar[it].y);
            s[4] = tf32u(ar[it].z); s[6] = tf32u(ar[it].w);
        }
        #pragma unroll
        for (int it = 0; it < 2; it++) {
            int idx = tid + it * 256;
            int r = idx >> 3, c4 = idx & 7;
            int ks = c4 >> 1, h = c4 & 1;
            uint32_t* s2 = &Bs[r][ks * 8 + h];
            s2[0] = tf32u(br[it].x); s2[2] = tf32u(br[it].y);
            s2[4] = tf32u(br[it].z); s2[6] = tf32u(br[it].w);
        }
    };

    loadA(0); loadB(0);
    for (int cc = 0; cc < N_ / 32; cc++) {
        stsAll();
        __syncthreads();
        if (cc + 1 < N_ / 32) { loadA((cc + 1) * 32); loadB((cc + 1) * 32); }

        #pragma unroll
        for (int ks = 0; ks < 4; ks++) {
            uint32_t bfr[4][2];
            #pragma unroll
            for (int nt = 0; nt < 4; nt++) {
                uint2 t = *reinterpret_cast<const uint2*>(&Bs[wc * 32 + nt * 8 + gid][ks * 8 + tig * 2]);
                bfr[nt][0] = t.x; bfr[nt][1] = t.y;
            }
            uint32_t afr[2][4];
            #pragma unroll
            for (int mt = 0; mt < 2; mt++) {
                int r0 = wr * 32 + mt * 16 + gid;
                uint2 t0 = *reinterpret_cast<const uint2*>(&As[r0][ks * 8 + tig * 2]);
                uint2 t1 = *reinterpret_cast<const uint2*>(&As[r0 + 8][ks * 8 + tig * 2]);
                afr[mt][0] = t0.x; afr[mt][2] = t0.y;
                afr[mt][1] = t1.x; afr[mt][3] = t1.y;
            }
            #pragma unroll
            for (int mt = 0; mt < 2; mt++)
                #pragma unroll
                for (int nt = 0; nt < 4; nt++)
                    mma_tf32(c[mt][nt], afr[mt], bfr[nt]);
        }
        __syncthreads();
    }

    // Epilogue: out[b][n][kslot*64 + d]
    float* dst = out + (size_t)bIdx * N_ * OUTDIM + kslot * DKDIM;
    #pragma unroll
    for (int mt = 0; mt < 2; mt++) {
        int n0 = nBase + wr * 32 + mt * 16 + gid;
        #pragma unroll
        for (int nt = 0; nt < 4; nt++) {
            int d0 = wc * 32 + nt * 8 + tig * 2;
            float2 v0 = make_float2(c[mt][nt][0], c[mt][nt][1]);
            float2 v1 = make_float2(c[mt][nt][2], c[mt][nt][3]);
            *reinterpret_cast<float2*>(dst + (size_t)n0 * OUTDIM + d0)       = v0;
            *reinterpret_cast<float2*>(dst + (size_t)(n0 + 8) * OUTDIM + d0) = v1;
        }
    }
}

// ---------------------------------------------------------------------------
extern "C" void kernel_launch(void* const* d_in, const int* in_sizes, int n_in,
                              void* d_out, int out_size)
{
    const float* node_feats = (const float*)d_in[0];  // (64,256,512)
    const float* adj        = (const float*)d_in[1];  // (64,8,256,256)
    const float* weight     = (const float*)d_in[2];  // (512,512)
    const float* bias       = (const float*)d_in[3];  // (512,)
    float* out = (float*)d_out;

    float *HT, *WT;
    cudaGetSymbolAddress((void**)&HT, g_ht);
    cudaGetSymbolAddress((void**)&WT, g_wt);

    wt_kernel<<<dim3(OUTDIM / 32, INDIM / 32), dim3(32, 8)>>>(weight, WT);
    s1_linear_mma<<<dim3(OUTDIM / 128, (B_ * N_) / 128), 256>>>(node_feats, WT, bias, HT);
    s2_aggregate_mma<<<dim3(N_ / 128, KSLOT, B_), 256>>>(adj, HT, out);
}